// round 5
// baseline (speedup 1.0000x reference)
#include <cuda_runtime.h>
#include <cstdint>

#define EPS 1e-7f
#define MAX_BLOCKS 4096
#define NTHREADS 256

// Per-block partials (fully overwritten each run -> no init kernel needed).
// .x = mse_sum, .y = iou_sum, .z = bit-cast n_inc, .w = bit-cast n_corr
__device__ float4 g_partials[MAX_BLOCKS];
__device__ unsigned int g_count;  // zero-init at load; reset to 0 after each use

__global__ void __launch_bounds__(NTHREADS) iou_fused_kernel(
    const float4* __restrict__ pr,
    const float4* __restrict__ gt,
    int n,
    float* __restrict__ out)
{
    float mse_sum = 0.f;
    float iou_sum = 0.f;
    unsigned int n_inc = 0;
    unsigned int n_corr = 0;

    // === R1's exact main loop: branchy body, __ldg, simple grid-stride ===
    int stride = gridDim.x * blockDim.x;
    for (int i = blockIdx.x * blockDim.x + threadIdx.x; i < n; i += stride) {
        float4 p = __ldg(&pr[i]);
        float4 g = __ldg(&gt[i]);

        // gt corners
        float x_min_t = g.x - g.z * 0.5f;
        float x_max_t = g.x + g.z * 0.5f;
        float y_min_t = g.y - g.w * 0.5f;
        float y_max_t = g.y + g.w * 0.5f;
        // pred corners, clipped to [0,1]
        float x_min_p = fmaxf(p.x - p.z * 0.5f, 0.0f);
        float x_max_p = fminf(p.x + p.z * 0.5f, 1.0f);
        float y_min_p = fmaxf(p.y - p.w * 0.5f, 0.0f);
        float y_max_p = fminf(p.y + p.w * 0.5f, 1.0f);
        // overlap box
        float o0 = fmaxf(x_min_t, x_min_p);
        float o1 = fmaxf(y_min_t, y_min_p);
        float o2 = fminf(x_max_t, x_max_p);
        float o3 = fminf(y_max_t, y_max_p);

        bool incorrect = (o2 < o0) || (o3 < o1);
        if (incorrect) {
            float dx = p.x - g.x, dy = p.y - g.y, dz = p.z - g.z, dw = p.w - g.w;
            mse_sum += dx * dx + dy * dy + dz * dz + dw * dw;
            n_inc++;
        } else {
            float area_p = p.z * p.w;
            float area_g = g.z * g.w;
            float inter = (o2 - o0) * (o3 - o1);
            float iou = inter / (area_p + area_g - inter + EPS);
            iou_sum += iou;
            n_corr++;
        }
    }

    // ---- block reduction (same as R1) ----
    #pragma unroll
    for (int off = 16; off > 0; off >>= 1) {
        mse_sum += __shfl_down_sync(0xffffffffu, mse_sum, off);
        iou_sum += __shfl_down_sync(0xffffffffu, iou_sum, off);
        n_inc   += __shfl_down_sync(0xffffffffu, n_inc, off);
        n_corr  += __shfl_down_sync(0xffffffffu, n_corr, off);
    }

    __shared__ float s_mse[8], s_iou[8];
    __shared__ unsigned int s_inc[8], s_corr[8];
    __shared__ bool s_is_last;
    int lane = threadIdx.x & 31;
    int wid = threadIdx.x >> 5;
    if (lane == 0) {
        s_mse[wid] = mse_sum;
        s_iou[wid] = iou_sum;
        s_inc[wid] = n_inc;
        s_corr[wid] = n_corr;
    }
    __syncthreads();
    if (wid == 0) {
        mse_sum = (lane < 8) ? s_mse[lane] : 0.f;
        iou_sum = (lane < 8) ? s_iou[lane] : 0.f;
        n_inc   = (lane < 8) ? s_inc[lane] : 0u;
        n_corr  = (lane < 8) ? s_corr[lane] : 0u;
        #pragma unroll
        for (int off = 4; off > 0; off >>= 1) {
            mse_sum += __shfl_down_sync(0xffu, mse_sum, off);
            iou_sum += __shfl_down_sync(0xffu, iou_sum, off);
            n_inc   += __shfl_down_sync(0xffu, n_inc, off);
            n_corr  += __shfl_down_sync(0xffu, n_corr, off);
        }
        if (lane == 0) {
            g_partials[blockIdx.x] = make_float4(
                mse_sum, iou_sum, __uint_as_float(n_inc), __uint_as_float(n_corr));
            __threadfence();
            unsigned int v = atomicAdd(&g_count, 1u);
            s_is_last = (v == gridDim.x - 1);
        }
    }
    __syncthreads();

    // ---- last block finalizes ----
    if (s_is_last) {
        double dmse = 0.0, diou = 0.0;
        unsigned long long dinc = 0ull, dcorr = 0ull;
        for (int j = threadIdx.x; j < gridDim.x; j += blockDim.x) {
            float4 v = g_partials[j];
            dmse  += (double)v.x;
            diou  += (double)v.y;
            dinc  += (unsigned long long)__float_as_uint(v.z);
            dcorr += (unsigned long long)__float_as_uint(v.w);
        }
        #pragma unroll
        for (int off = 16; off > 0; off >>= 1) {
            dmse  += __shfl_down_sync(0xffffffffu, dmse, off);
            diou  += __shfl_down_sync(0xffffffffu, diou, off);
            dinc  += __shfl_down_sync(0xffffffffu, dinc, off);
            dcorr += __shfl_down_sync(0xffffffffu, dcorr, off);
        }
        __shared__ double f_mse[8], f_iou[8];
        __shared__ unsigned long long f_inc[8], f_corr[8];
        if (lane == 0) {
            f_mse[wid] = dmse;
            f_iou[wid] = diou;
            f_inc[wid] = dinc;
            f_corr[wid] = dcorr;
        }
        __syncthreads();
        if (threadIdx.x == 0) {
            dmse = 0.0; diou = 0.0; dinc = 0ull; dcorr = 0ull;
            #pragma unroll
            for (int w = 0; w < 8; w++) {
                dmse  += f_mse[w];
                diou  += f_iou[w];
                dinc  += f_inc[w];
                dcorr += f_corr[w];
            }
            double denom_mse = (double)(dinc * 4ull > 0ull ? dinc * 4ull : 1ull);
            double mse_mean = dmse / denom_mse;
            double denom_iou = (double)(dcorr > 0ull ? dcorr : 1ull);
            double iou_mean = diou / denom_iou;

            double res_full = iou_mean + (dinc > 0ull ? -mse_mean : 0.0);
            double res = (dcorr > 0ull) ? res_full : -mse_mean;
            out[0] = (float)res;

            g_count = 0u;  // reset for next graph replay
        }
    }
}

extern "C" void kernel_launch(void* const* d_in, const int* in_sizes, int n_in,
                              void* d_out, int out_size) {
    const float4* pr = (const float4*)d_in[0];
    const float4* gt = (const float4*)d_in[1];
    int n = in_sizes[0] / 4;  // boxes

    int blocks = 2048;  // R1's winning config
    if (blocks > MAX_BLOCKS) blocks = MAX_BLOCKS;
    int maxNeeded = (n + NTHREADS - 1) / NTHREADS;
    if (blocks > maxNeeded) blocks = maxNeeded;

    iou_fused_kernel<<<blocks, NTHREADS>>>(pr, gt, n, (float*)d_out);
}

// round 6
// speedup vs baseline: 1.0013x; 1.0013x over previous
#include <cuda_runtime.h>
#include <cstdint>

#define EPS 1e-7f
#define MAX_BLOCKS 4096
#define NTHREADS 256

// Per-block partials (fully overwritten each run -> no init kernel needed).
// .x = mse_sum, .y = iou_sum, .z = bit-cast n_inc, .w = bit-cast n_corr
__device__ float4 g_partials[MAX_BLOCKS];
__device__ unsigned int g_count;  // zero-init at load; reset to 0 after each use

__device__ __forceinline__ void process_box(
    const float4 p, const float4 g,
    float& mse_sum, float& iou_sum,
    unsigned int& n_inc, unsigned int& n_corr)
{
    // gt corners
    float x_min_t = g.x - g.z * 0.5f;
    float x_max_t = g.x + g.z * 0.5f;
    float y_min_t = g.y - g.w * 0.5f;
    float y_max_t = g.y + g.w * 0.5f;
    // pred corners, clipped to [0,1]
    float x_min_p = fmaxf(p.x - p.z * 0.5f, 0.0f);
    float x_max_p = fminf(p.x + p.z * 0.5f, 1.0f);
    float y_min_p = fmaxf(p.y - p.w * 0.5f, 0.0f);
    float y_max_p = fminf(p.y + p.w * 0.5f, 1.0f);
    // overlap box
    float o0 = fmaxf(x_min_t, x_min_p);
    float o1 = fmaxf(y_min_t, y_min_p);
    float o2 = fminf(x_max_t, x_max_p);
    float o3 = fminf(y_max_t, y_max_p);

    bool incorrect = (o2 < o0) || (o3 < o1);
    if (incorrect) {
        float dx = p.x - g.x, dy = p.y - g.y, dz = p.z - g.z, dw = p.w - g.w;
        mse_sum += dx * dx + dy * dy + dz * dz + dw * dw;
        n_inc++;
    } else {
        float area_p = p.z * p.w;
        float area_g = g.z * g.w;
        float inter = (o2 - o0) * (o3 - o1);
        float iou = inter / (area_p + area_g - inter + EPS);
        iou_sum += iou;
        n_corr++;
    }
}

__global__ void __launch_bounds__(NTHREADS) iou_fused_kernel(
    const float4* __restrict__ pr,
    const float4* __restrict__ gt,
    int n,
    float* __restrict__ out)
{
    float mse_sum = 0.f;
    float iou_sum = 0.f;
    unsigned int n_inc = 0;
    unsigned int n_corr = 0;

    const int stride = gridDim.x * blockDim.x;
    int i = blockIdx.x * blockDim.x + threadIdx.x;

    // Software-pipelined grid-stride loop. Same addresses & order as the
    // simple loop; next iteration's loads are issued BEFORE processing the
    // current one so the compute window overlaps the memory latency.
    if (i < n) {
        float4 p = __ldg(&pr[i]);
        float4 g = __ldg(&gt[i]);
        int inext = i + stride;
        while (inext < n) {
            float4 p2 = __ldg(&pr[inext]);
            float4 g2 = __ldg(&gt[inext]);
            process_box(p, g, mse_sum, iou_sum, n_inc, n_corr);
            p = p2; g = g2;
            inext += stride;
        }
        process_box(p, g, mse_sum, iou_sum, n_inc, n_corr);
    }

    // ---- block reduction ----
    #pragma unroll
    for (int off = 16; off > 0; off >>= 1) {
        mse_sum += __shfl_down_sync(0xffffffffu, mse_sum, off);
        iou_sum += __shfl_down_sync(0xffffffffu, iou_sum, off);
        n_inc   += __shfl_down_sync(0xffffffffu, n_inc, off);
        n_corr  += __shfl_down_sync(0xffffffffu, n_corr, off);
    }

    __shared__ float s_mse[8], s_iou[8];
    __shared__ unsigned int s_inc[8], s_corr[8];
    __shared__ bool s_is_last;
    int lane = threadIdx.x & 31;
    int wid = threadIdx.x >> 5;
    if (lane == 0) {
        s_mse[wid] = mse_sum;
        s_iou[wid] = iou_sum;
        s_inc[wid] = n_inc;
        s_corr[wid] = n_corr;
    }
    __syncthreads();
    if (wid == 0) {
        mse_sum = (lane < 8) ? s_mse[lane] : 0.f;
        iou_sum = (lane < 8) ? s_iou[lane] : 0.f;
        n_inc   = (lane < 8) ? s_inc[lane] : 0u;
        n_corr  = (lane < 8) ? s_corr[lane] : 0u;
        #pragma unroll
        for (int off = 4; off > 0; off >>= 1) {
            mse_sum += __shfl_down_sync(0xffu, mse_sum, off);
            iou_sum += __shfl_down_sync(0xffu, iou_sum, off);
            n_inc   += __shfl_down_sync(0xffu, n_inc, off);
            n_corr  += __shfl_down_sync(0xffu, n_corr, off);
        }
        if (lane == 0) {
            g_partials[blockIdx.x] = make_float4(
                mse_sum, iou_sum, __uint_as_float(n_inc), __uint_as_float(n_corr));
            __threadfence();
            unsigned int v = atomicAdd(&g_count, 1u);
            s_is_last = (v == gridDim.x - 1);
        }
    }
    __syncthreads();

    // ---- last block finalizes ----
    if (s_is_last) {
        double dmse = 0.0, diou = 0.0;
        unsigned long long dinc = 0ull, dcorr = 0ull;
        for (int j = threadIdx.x; j < gridDim.x; j += blockDim.x) {
            float4 v = g_partials[j];
            dmse  += (double)v.x;
            diou  += (double)v.y;
            dinc  += (unsigned long long)__float_as_uint(v.z);
            dcorr += (unsigned long long)__float_as_uint(v.w);
        }
        #pragma unroll
        for (int off = 16; off > 0; off >>= 1) {
            dmse  += __shfl_down_sync(0xffffffffu, dmse, off);
            diou  += __shfl_down_sync(0xffffffffu, diou, off);
            dinc  += __shfl_down_sync(0xffffffffu, dinc, off);
            dcorr += __shfl_down_sync(0xffffffffu, dcorr, off);
        }
        __shared__ double f_mse[8], f_iou[8];
        __shared__ unsigned long long f_inc[8], f_corr[8];
        if (lane == 0) {
            f_mse[wid] = dmse;
            f_iou[wid] = diou;
            f_inc[wid] = dinc;
            f_corr[wid] = dcorr;
        }
        __syncthreads();
        if (threadIdx.x == 0) {
            dmse = 0.0; diou = 0.0; dinc = 0ull; dcorr = 0ull;
            #pragma unroll
            for (int w = 0; w < 8; w++) {
                dmse  += f_mse[w];
                diou  += f_iou[w];
                dinc  += f_inc[w];
                dcorr += f_corr[w];
            }
            double denom_mse = (double)(dinc * 4ull > 0ull ? dinc * 4ull : 1ull);
            double mse_mean = dmse / denom_mse;
            double denom_iou = (double)(dcorr > 0ull ? dcorr : 1ull);
            double iou_mean = diou / denom_iou;

            double res_full = iou_mean + (dinc > 0ull ? -mse_mean : 0.0);
            double res = (dcorr > 0ull) ? res_full : -mse_mean;
            out[0] = (float)res;

            g_count = 0u;  // reset for next graph replay
        }
    }
}

extern "C" void kernel_launch(void* const* d_in, const int* in_sizes, int n_in,
                              void* d_out, int out_size) {
    const float4* pr = (const float4*)d_in[0];
    const float4* gt = (const float4*)d_in[1];
    int n = in_sizes[0] / 4;  // boxes

    int blocks = 2048;
    if (blocks > MAX_BLOCKS) blocks = MAX_BLOCKS;
    int maxNeeded = (n + NTHREADS - 1) / NTHREADS;
    if (blocks > maxNeeded) blocks = maxNeeded;

    iou_fused_kernel<<<blocks, NTHREADS>>>(pr, gt, n, (float*)d_out);
}

// round 7
// speedup vs baseline: 1.0498x; 1.0484x over previous
#include <cuda_runtime.h>
#include <cstdint>

#define EPS 1e-7f
#define MAX_BLOCKS 4096
#define NTHREADS 256
#define GRID_BLOCKS 1216   // 152 SMs x 8 resident CTAs -> exactly one wave

// Per-block partials (fully overwritten each run -> no init kernel needed).
// .x = mse_sum, .y = iou_sum, .z = bit-cast n_inc, .w = bit-cast n_corr
__device__ float4 g_partials[MAX_BLOCKS];
__device__ unsigned int g_count;  // zero-init at load; reset to 0 after each use

__device__ __forceinline__ void process_box(
    const float4 p, const float4 g,
    float& mse_sum, float& iou_sum,
    unsigned int& n_inc, unsigned int& n_corr)
{
    // gt corners
    float x_min_t = g.x - g.z * 0.5f;
    float x_max_t = g.x + g.z * 0.5f;
    float y_min_t = g.y - g.w * 0.5f;
    float y_max_t = g.y + g.w * 0.5f;
    // pred corners, clipped to [0,1]
    float x_min_p = fmaxf(p.x - p.z * 0.5f, 0.0f);
    float x_max_p = fminf(p.x + p.z * 0.5f, 1.0f);
    float y_min_p = fmaxf(p.y - p.w * 0.5f, 0.0f);
    float y_max_p = fminf(p.y + p.w * 0.5f, 1.0f);
    // overlap box
    float o0 = fmaxf(x_min_t, x_min_p);
    float o1 = fmaxf(y_min_t, y_min_p);
    float o2 = fminf(x_max_t, x_max_p);
    float o3 = fminf(y_max_t, y_max_p);

    bool incorrect = (o2 < o0) || (o3 < o1);
    if (incorrect) {
        float dx = p.x - g.x, dy = p.y - g.y, dz = p.z - g.z, dw = p.w - g.w;
        mse_sum += dx * dx + dy * dy + dz * dz + dw * dw;
        n_inc++;
    } else {
        float area_p = p.z * p.w;
        float area_g = g.z * g.w;
        float inter = (o2 - o0) * (o3 - o1);
        float iou = inter / (area_p + area_g - inter + EPS);
        iou_sum += iou;
        n_corr++;
    }
}

__global__ void __launch_bounds__(NTHREADS) iou_fused_kernel(
    const float4* __restrict__ pr,
    const float4* __restrict__ gt,
    int n,
    float* __restrict__ out)
{
    float mse_sum = 0.f;
    float iou_sum = 0.f;
    unsigned int n_inc = 0;
    unsigned int n_corr = 0;

    const int stride = gridDim.x * blockDim.x;
    int i = blockIdx.x * blockDim.x + threadIdx.x;

    // Software-pipelined grid-stride loop (same addresses/order as the
    // simple loop; next iteration's loads issued before processing current).
    if (i < n) {
        float4 p = __ldg(&pr[i]);
        float4 g = __ldg(&gt[i]);
        int inext = i + stride;
        while (inext < n) {
            float4 p2 = __ldg(&pr[inext]);
            float4 g2 = __ldg(&gt[inext]);
            process_box(p, g, mse_sum, iou_sum, n_inc, n_corr);
            p = p2; g = g2;
            inext += stride;
        }
        process_box(p, g, mse_sum, iou_sum, n_inc, n_corr);
    }

    // ---- block reduction ----
    #pragma unroll
    for (int off = 16; off > 0; off >>= 1) {
        mse_sum += __shfl_down_sync(0xffffffffu, mse_sum, off);
        iou_sum += __shfl_down_sync(0xffffffffu, iou_sum, off);
        n_inc   += __shfl_down_sync(0xffffffffu, n_inc, off);
        n_corr  += __shfl_down_sync(0xffffffffu, n_corr, off);
    }

    __shared__ float s_mse[8], s_iou[8];
    __shared__ unsigned int s_inc[8], s_corr[8];
    __shared__ bool s_is_last;
    int lane = threadIdx.x & 31;
    int wid = threadIdx.x >> 5;
    if (lane == 0) {
        s_mse[wid] = mse_sum;
        s_iou[wid] = iou_sum;
        s_inc[wid] = n_inc;
        s_corr[wid] = n_corr;
    }
    __syncthreads();
    if (wid == 0) {
        mse_sum = (lane < 8) ? s_mse[lane] : 0.f;
        iou_sum = (lane < 8) ? s_iou[lane] : 0.f;
        n_inc   = (lane < 8) ? s_inc[lane] : 0u;
        n_corr  = (lane < 8) ? s_corr[lane] : 0u;
        #pragma unroll
        for (int off = 4; off > 0; off >>= 1) {
            mse_sum += __shfl_down_sync(0xffu, mse_sum, off);
            iou_sum += __shfl_down_sync(0xffu, iou_sum, off);
            n_inc   += __shfl_down_sync(0xffu, n_inc, off);
            n_corr  += __shfl_down_sync(0xffu, n_corr, off);
        }
        if (lane == 0) {
            g_partials[blockIdx.x] = make_float4(
                mse_sum, iou_sum, __uint_as_float(n_inc), __uint_as_float(n_corr));
            __threadfence();
            unsigned int v = atomicAdd(&g_count, 1u);
            s_is_last = (v == gridDim.x - 1);
        }
    }
    __syncthreads();

    // ---- last block finalizes ----
    if (s_is_last) {
        double dmse = 0.0, diou = 0.0;
        unsigned long long dinc = 0ull, dcorr = 0ull;
        for (int j = threadIdx.x; j < gridDim.x; j += blockDim.x) {
            float4 v = g_partials[j];
            dmse  += (double)v.x;
            diou  += (double)v.y;
            dinc  += (unsigned long long)__float_as_uint(v.z);
            dcorr += (unsigned long long)__float_as_uint(v.w);
        }
        #pragma unroll
        for (int off = 16; off > 0; off >>= 1) {
            dmse  += __shfl_down_sync(0xffffffffu, dmse, off);
            diou  += __shfl_down_sync(0xffffffffu, diou, off);
            dinc  += __shfl_down_sync(0xffffffffu, dinc, off);
            dcorr += __shfl_down_sync(0xffffffffu, dcorr, off);
        }
        __shared__ double f_mse[8], f_iou[8];
        __shared__ unsigned long long f_inc[8], f_corr[8];
        if (lane == 0) {
            f_mse[wid] = dmse;
            f_iou[wid] = diou;
            f_inc[wid] = dinc;
            f_corr[wid] = dcorr;
        }
        __syncthreads();
        if (threadIdx.x == 0) {
            dmse = 0.0; diou = 0.0; dinc = 0ull; dcorr = 0ull;
            #pragma unroll
            for (int w = 0; w < 8; w++) {
                dmse  += f_mse[w];
                diou  += f_iou[w];
                dinc  += f_inc[w];
                dcorr += f_corr[w];
            }
            double denom_mse = (double)(dinc * 4ull > 0ull ? dinc * 4ull : 1ull);
            double mse_mean = dmse / denom_mse;
            double denom_iou = (double)(dcorr > 0ull ? dcorr : 1ull);
            double iou_mean = diou / denom_iou;

            double res_full = iou_mean + (dinc > 0ull ? -mse_mean : 0.0);
            double res = (dcorr > 0ull) ? res_full : -mse_mean;
            out[0] = (float)res;

            g_count = 0u;  // reset for next graph replay
        }
    }
}

extern "C" void kernel_launch(void* const* d_in, const int* in_sizes, int n_in,
                              void* d_out, int out_size) {
    const float4* pr = (const float4*)d_in[0];
    const float4* gt = (const float4*)d_in[1];
    int n = in_sizes[0] / 4;  // boxes

    int blocks = GRID_BLOCKS;  // exactly one resident wave (152 SMs x 8 CTAs)
    int maxNeeded = (n + NTHREADS - 1) / NTHREADS;
    if (blocks > maxNeeded) blocks = maxNeeded;

    iou_fused_kernel<<<blocks, NTHREADS>>>(pr, gt, n, (float*)d_out);
}

// round 8
// speedup vs baseline: 1.0505x; 1.0007x over previous
#include <cuda_runtime.h>
#include <cstdint>

#define EPS 1e-7f
#define MAX_BLOCKS 4096
#define NTHREADS 256
#define GRID_BLOCKS 912   // 152 SMs x 6 resident CTAs -> exactly one wave

// Per-block partials (fully overwritten each run -> no init kernel needed).
// .x = mse_sum, .y = iou_sum, .z = bit-cast n_inc, .w = bit-cast n_corr
__device__ float4 g_partials[MAX_BLOCKS];
__device__ unsigned int g_count;  // zero-init at load; reset to 0 after each use

__device__ __forceinline__ void process_box(
    const float4 p, const float4 g,
    float& mse_sum, float& iou_sum,
    unsigned int& n_inc, unsigned int& n_corr)
{
    // gt corners
    float x_min_t = g.x - g.z * 0.5f;
    float x_max_t = g.x + g.z * 0.5f;
    float y_min_t = g.y - g.w * 0.5f;
    float y_max_t = g.y + g.w * 0.5f;
    // pred corners, clipped to [0,1]
    float x_min_p = fmaxf(p.x - p.z * 0.5f, 0.0f);
    float x_max_p = fminf(p.x + p.z * 0.5f, 1.0f);
    float y_min_p = fmaxf(p.y - p.w * 0.5f, 0.0f);
    float y_max_p = fminf(p.y + p.w * 0.5f, 1.0f);
    // overlap box
    float o0 = fmaxf(x_min_t, x_min_p);
    float o1 = fmaxf(y_min_t, y_min_p);
    float o2 = fminf(x_max_t, x_max_p);
    float o3 = fminf(y_max_t, y_max_p);

    bool incorrect = (o2 < o0) || (o3 < o1);
    if (incorrect) {
        float dx = p.x - g.x, dy = p.y - g.y, dz = p.z - g.z, dw = p.w - g.w;
        mse_sum += dx * dx + dy * dy + dz * dz + dw * dw;
        n_inc++;
    } else {
        float area_p = p.z * p.w;
        float area_g = g.z * g.w;
        float inter = (o2 - o0) * (o3 - o1);
        float iou = inter / (area_p + area_g - inter + EPS);
        iou_sum += iou;
        n_corr++;
    }
}

__global__ void __launch_bounds__(NTHREADS, 6) iou_fused_kernel(
    const float4* __restrict__ pr,
    const float4* __restrict__ gt,
    int n,
    float* __restrict__ out)
{
    float mse_sum = 0.f;
    float iou_sum = 0.f;
    unsigned int n_inc = 0;
    unsigned int n_corr = 0;

    // Pair-per-thread: each iteration loads 2 ADJACENT boxes from each array
    // (warp covers 1024B contiguous per stream; MLP=4 with no extra streams).
    const int gridtotal = gridDim.x * blockDim.x;
    const int npairs = n >> 1;            // n is even (8M); scalar tail below
    int j = blockIdx.x * blockDim.x + threadIdx.x;
    for (; j < npairs; j += gridtotal) {
        int i = j << 1;
        float4 p0 = __ldg(&pr[i]);
        float4 p1 = __ldg(&pr[i + 1]);
        float4 g0 = __ldg(&gt[i]);
        float4 g1 = __ldg(&gt[i + 1]);
        process_box(p0, g0, mse_sum, iou_sum, n_inc, n_corr);
        process_box(p1, g1, mse_sum, iou_sum, n_inc, n_corr);
    }
    // odd-n tail (not hit for 8M, kept for generality)
    if ((n & 1) && (blockIdx.x == 0) && (threadIdx.x == 0)) {
        float4 p = __ldg(&pr[n - 1]);
        float4 g = __ldg(&gt[n - 1]);
        process_box(p, g, mse_sum, iou_sum, n_inc, n_corr);
    }

    // ---- block reduction ----
    #pragma unroll
    for (int off = 16; off > 0; off >>= 1) {
        mse_sum += __shfl_down_sync(0xffffffffu, mse_sum, off);
        iou_sum += __shfl_down_sync(0xffffffffu, iou_sum, off);
        n_inc   += __shfl_down_sync(0xffffffffu, n_inc, off);
        n_corr  += __shfl_down_sync(0xffffffffu, n_corr, off);
    }

    __shared__ float s_mse[8], s_iou[8];
    __shared__ unsigned int s_inc[8], s_corr[8];
    __shared__ bool s_is_last;
    int lane = threadIdx.x & 31;
    int wid = threadIdx.x >> 5;
    if (lane == 0) {
        s_mse[wid] = mse_sum;
        s_iou[wid] = iou_sum;
        s_inc[wid] = n_inc;
        s_corr[wid] = n_corr;
    }
    __syncthreads();
    if (wid == 0) {
        mse_sum = (lane < 8) ? s_mse[lane] : 0.f;
        iou_sum = (lane < 8) ? s_iou[lane] : 0.f;
        n_inc   = (lane < 8) ? s_inc[lane] : 0u;
        n_corr  = (lane < 8) ? s_corr[lane] : 0u;
        #pragma unroll
        for (int off = 4; off > 0; off >>= 1) {
            mse_sum += __shfl_down_sync(0xffu, mse_sum, off);
            iou_sum += __shfl_down_sync(0xffu, iou_sum, off);
            n_inc   += __shfl_down_sync(0xffu, n_inc, off);
            n_corr  += __shfl_down_sync(0xffu, n_corr, off);
        }
        if (lane == 0) {
            g_partials[blockIdx.x] = make_float4(
                mse_sum, iou_sum, __uint_as_float(n_inc), __uint_as_float(n_corr));
            __threadfence();
            unsigned int v = atomicAdd(&g_count, 1u);
            s_is_last = (v == gridDim.x - 1);
        }
    }
    __syncthreads();

    // ---- last block finalizes ----
    if (s_is_last) {
        double dmse = 0.0, diou = 0.0;
        unsigned long long dinc = 0ull, dcorr = 0ull;
        for (int k = threadIdx.x; k < gridDim.x; k += blockDim.x) {
            float4 v = g_partials[k];
            dmse  += (double)v.x;
            diou  += (double)v.y;
            dinc  += (unsigned long long)__float_as_uint(v.z);
            dcorr += (unsigned long long)__float_as_uint(v.w);
        }
        #pragma unroll
        for (int off = 16; off > 0; off >>= 1) {
            dmse  += __shfl_down_sync(0xffffffffu, dmse, off);
            diou  += __shfl_down_sync(0xffffffffu, diou, off);
            dinc  += __shfl_down_sync(0xffffffffu, dinc, off);
            dcorr += __shfl_down_sync(0xffffffffu, dcorr, off);
        }
        __shared__ double f_mse[8], f_iou[8];
        __shared__ unsigned long long f_inc[8], f_corr[8];
        if (lane == 0) {
            f_mse[wid] = dmse;
            f_iou[wid] = diou;
            f_inc[wid] = dinc;
            f_corr[wid] = dcorr;
        }
        __syncthreads();
        if (threadIdx.x == 0) {
            dmse = 0.0; diou = 0.0; dinc = 0ull; dcorr = 0ull;
            #pragma unroll
            for (int w = 0; w < 8; w++) {
                dmse  += f_mse[w];
                diou  += f_iou[w];
                dinc  += f_inc[w];
                dcorr += f_corr[w];
            }
            double denom_mse = (double)(dinc * 4ull > 0ull ? dinc * 4ull : 1ull);
            double mse_mean = dmse / denom_mse;
            double denom_iou = (double)(dcorr > 0ull ? dcorr : 1ull);
            double iou_mean = diou / denom_iou;

            double res_full = iou_mean + (dinc > 0ull ? -mse_mean : 0.0);
            double res = (dcorr > 0ull) ? res_full : -mse_mean;
            out[0] = (float)res;

            g_count = 0u;  // reset for next graph replay
        }
    }
}

extern "C" void kernel_launch(void* const* d_in, const int* in_sizes, int n_in,
                              void* d_out, int out_size) {
    const float4* pr = (const float4*)d_in[0];
    const float4* gt = (const float4*)d_in[1];
    int n = in_sizes[0] / 4;  // boxes

    int blocks = GRID_BLOCKS;  // one resident wave at 6 CTAs/SM
    int maxNeeded = ((n >> 1) + NTHREADS - 1) / NTHREADS;
    if (maxNeeded < 1) maxNeeded = 1;
    if (blocks > maxNeeded) blocks = maxNeeded;

    iou_fused_kernel<<<blocks, NTHREADS>>>(pr, gt, n, (float*)d_out);
}

// round 9
// speedup vs baseline: 1.0684x; 1.0171x over previous
#include <cuda_runtime.h>
#include <cstdint>

#define EPS 1e-7f
#define MAX_BLOCKS 4096
#define NTHREADS 256
#define GRID_BLOCKS 304          // 152 SMs x 2 CTAs (smem-limited) -> one wave
#define TILE 1024                // boxes per tile
#define TILE_BYTES (TILE * 16)   // 16 KB per array per tile
#define STAGE_BYTES (2 * TILE_BYTES)
#define STAGES 3
#define SMEM_BAR_OFF (STAGES * STAGE_BYTES)      // 98304
#define SMEM_TOTAL (SMEM_BAR_OFF + 64)

// Per-block partials. .x=mse, .y=iou, .z=bitcast n_inc, .w=bitcast n_corr
__device__ float4 g_partials[MAX_BLOCKS];
__device__ unsigned int g_count;  // zero-init at load; reset after each use

__device__ __forceinline__ uint32_t smem_u32(const void* p) {
    uint32_t a;
    asm("{ .reg .u64 t; cvta.to.shared.u64 t, %1; cvt.u32.u64 %0, t; }" : "=r"(a) : "l"(p));
    return a;
}

__device__ __forceinline__ void bulk_g2s(uint32_t dst, const void* src,
                                         uint32_t bytes, uint32_t mbar) {
    asm volatile(
        "cp.async.bulk.shared::cta.global.mbarrier::complete_tx::bytes [%0], [%1], %2, [%3];"
        :: "r"(dst), "l"(src), "r"(bytes), "r"(mbar) : "memory");
}

__device__ __forceinline__ void mbar_init(uint32_t mbar, uint32_t count) {
    asm volatile("mbarrier.init.shared.b64 [%0], %1;" :: "r"(mbar), "r"(count) : "memory");
}

__device__ __forceinline__ void mbar_expect_tx(uint32_t mbar, uint32_t bytes) {
    asm volatile("mbarrier.arrive.expect_tx.shared.b64 _, [%0], %1;"
                 :: "r"(mbar), "r"(bytes) : "memory");
}

__device__ __forceinline__ void mbar_wait(uint32_t mbar, uint32_t parity) {
    uint32_t done;
    asm volatile(
        "{\n\t.reg .pred p;\n\t"
        "mbarrier.try_wait.parity.acquire.cta.shared::cta.b64 p, [%1], %2;\n\t"
        "selp.b32 %0, 1, 0, p;\n\t}"
        : "=r"(done) : "r"(mbar), "r"(parity) : "memory");
    if (!done) {
        asm volatile(
            "{\n\t.reg .pred P1;\n\t"
            "WAIT_LOOP_%=:\n\t"
            "mbarrier.try_wait.parity.acquire.cta.shared::cta.b64 P1, [%0], %1, 0x989680;\n\t"
            "@P1 bra.uni WAIT_DONE_%=;\n\t"
            "bra.uni WAIT_LOOP_%=;\n\t"
            "WAIT_DONE_%=:\n\t}"
            :: "r"(mbar), "r"(parity) : "memory");
    }
}

__device__ __forceinline__ void process_box(
    const float4 p, const float4 g,
    float& mse_sum, float& iou_sum,
    unsigned int& n_inc, unsigned int& n_corr)
{
    float x_min_t = g.x - g.z * 0.5f;
    float x_max_t = g.x + g.z * 0.5f;
    float y_min_t = g.y - g.w * 0.5f;
    float y_max_t = g.y + g.w * 0.5f;
    float x_min_p = fmaxf(p.x - p.z * 0.5f, 0.0f);
    float x_max_p = fminf(p.x + p.z * 0.5f, 1.0f);
    float y_min_p = fmaxf(p.y - p.w * 0.5f, 0.0f);
    float y_max_p = fminf(p.y + p.w * 0.5f, 1.0f);
    float o0 = fmaxf(x_min_t, x_min_p);
    float o1 = fmaxf(y_min_t, y_min_p);
    float o2 = fminf(x_max_t, x_max_p);
    float o3 = fminf(y_max_t, y_max_p);

    bool incorrect = (o2 < o0) || (o3 < o1);
    if (incorrect) {
        float dx = p.x - g.x, dy = p.y - g.y, dz = p.z - g.z, dw = p.w - g.w;
        mse_sum += dx * dx + dy * dy + dz * dz + dw * dw;
        n_inc++;
    } else {
        float area_p = p.z * p.w;
        float area_g = g.z * g.w;
        float inter = (o2 - o0) * (o3 - o1);
        iou_sum += inter / (area_p + area_g - inter + EPS);
        n_corr++;
    }
}

__global__ void __launch_bounds__(NTHREADS, 2) iou_tma_kernel(
    const float4* __restrict__ pr,
    const float4* __restrict__ gt,
    int n,
    float* __restrict__ out)
{
    extern __shared__ char smem_raw[];
    const uint32_t smem_base = smem_u32(smem_raw);
    const int tid = threadIdx.x;
    const int bid = blockIdx.x;
    const int grid = gridDim.x;

    float mse_sum = 0.f;
    float iou_sum = 0.f;
    unsigned int n_inc = 0;
    unsigned int n_corr = 0;

    const int full_tiles = n / TILE;

    // ---- barrier init ----
    if (tid == 0) {
        #pragma unroll
        for (int s = 0; s < STAGES; s++)
            mbar_init(smem_base + SMEM_BAR_OFF + s * 8, 1);
        asm volatile("fence.proxy.async.shared::cta;" ::: "memory");
    }
    __syncthreads();

    // ---- prologue: issue up to STAGES tiles ----
    if (tid == 0) {
        #pragma unroll
        for (int k = 0; k < STAGES; k++) {
            long long t = (long long)bid + (long long)k * grid;
            if (t < full_tiles) {
                uint32_t mbar = smem_base + SMEM_BAR_OFF + k * 8;
                uint32_t dst = smem_base + k * STAGE_BYTES;
                mbar_expect_tx(mbar, STAGE_BYTES);
                bulk_g2s(dst, pr + t * TILE, TILE_BYTES, mbar);
                bulk_g2s(dst + TILE_BYTES, gt + t * TILE, TILE_BYTES, mbar);
            }
        }
    }

    // ---- main pipeline ----
    int k = 0;
    for (long long t = bid; t < full_tiles; t += grid, k++) {
        int s = k % STAGES;
        uint32_t parity = (uint32_t)((k / STAGES) & 1);
        uint32_t mbar = smem_base + SMEM_BAR_OFF + s * 8;
        mbar_wait(mbar, parity);

        const float4* pr_s = (const float4*)(smem_raw + s * STAGE_BYTES);
        const float4* gt_s = (const float4*)(smem_raw + s * STAGE_BYTES + TILE_BYTES);
        #pragma unroll
        for (int u = 0; u < TILE / NTHREADS; u++) {
            int j = tid + u * NTHREADS;
            float4 p = pr_s[j];
            float4 g = gt_s[j];
            process_box(p, g, mse_sum, iou_sum, n_inc, n_corr);
        }
        __syncthreads();  // all threads done reading stage s

        if (tid == 0) {
            long long tn = t + (long long)STAGES * grid;
            if (tn < full_tiles) {
                uint32_t dst = smem_base + s * STAGE_BYTES;
                mbar_expect_tx(mbar, STAGE_BYTES);
                bulk_g2s(dst, pr + tn * TILE, TILE_BYTES, mbar);
                bulk_g2s(dst + TILE_BYTES, gt + tn * TILE, TILE_BYTES, mbar);
            }
        }
    }

    // ---- tail (n % TILE boxes), block 0 via direct LDG ----
    if (bid == 0) {
        for (int i = full_tiles * TILE + tid; i < n; i += NTHREADS) {
            float4 p = __ldg(&pr[i]);
            float4 g = __ldg(&gt[i]);
            process_box(p, g, mse_sum, iou_sum, n_inc, n_corr);
        }
    }

    // ---- block reduction ----
    #pragma unroll
    for (int off = 16; off > 0; off >>= 1) {
        mse_sum += __shfl_down_sync(0xffffffffu, mse_sum, off);
        iou_sum += __shfl_down_sync(0xffffffffu, iou_sum, off);
        n_inc   += __shfl_down_sync(0xffffffffu, n_inc, off);
        n_corr  += __shfl_down_sync(0xffffffffu, n_corr, off);
    }

    __shared__ float s_mse[8], s_iou[8];
    __shared__ unsigned int s_inc[8], s_corr[8];
    __shared__ bool s_is_last;
    int lane = threadIdx.x & 31;
    int wid = threadIdx.x >> 5;
    if (lane == 0) {
        s_mse[wid] = mse_sum;
        s_iou[wid] = iou_sum;
        s_inc[wid] = n_inc;
        s_corr[wid] = n_corr;
    }
    __syncthreads();
    if (wid == 0) {
        mse_sum = (lane < 8) ? s_mse[lane] : 0.f;
        iou_sum = (lane < 8) ? s_iou[lane] : 0.f;
        n_inc   = (lane < 8) ? s_inc[lane] : 0u;
        n_corr  = (lane < 8) ? s_corr[lane] : 0u;
        #pragma unroll
        for (int off = 4; off > 0; off >>= 1) {
            mse_sum += __shfl_down_sync(0xffu, mse_sum, off);
            iou_sum += __shfl_down_sync(0xffu, iou_sum, off);
            n_inc   += __shfl_down_sync(0xffu, n_inc, off);
            n_corr  += __shfl_down_sync(0xffu, n_corr, off);
        }
        if (lane == 0) {
            g_partials[blockIdx.x] = make_float4(
                mse_sum, iou_sum, __uint_as_float(n_inc), __uint_as_float(n_corr));
            __threadfence();
            unsigned int v = atomicAdd(&g_count, 1u);
            s_is_last = (v == gridDim.x - 1);
        }
    }
    __syncthreads();

    // ---- last block finalizes ----
    if (s_is_last) {
        double dmse = 0.0, diou = 0.0;
        unsigned long long dinc = 0ull, dcorr = 0ull;
        for (int j2 = threadIdx.x; j2 < gridDim.x; j2 += blockDim.x) {
            float4 v = g_partials[j2];
            dmse  += (double)v.x;
            diou  += (double)v.y;
            dinc  += (unsigned long long)__float_as_uint(v.z);
            dcorr += (unsigned long long)__float_as_uint(v.w);
        }
        #pragma unroll
        for (int off = 16; off > 0; off >>= 1) {
            dmse  += __shfl_down_sync(0xffffffffu, dmse, off);
            diou  += __shfl_down_sync(0xffffffffu, diou, off);
            dinc  += __shfl_down_sync(0xffffffffu, dinc, off);
            dcorr += __shfl_down_sync(0xffffffffu, dcorr, off);
        }
        __shared__ double f_mse[8], f_iou[8];
        __shared__ unsigned long long f_inc[8], f_corr[8];
        if (lane == 0) {
            f_mse[wid] = dmse;
            f_iou[wid] = diou;
            f_inc[wid] = dinc;
            f_corr[wid] = dcorr;
        }
        __syncthreads();
        if (threadIdx.x == 0) {
            dmse = 0.0; diou = 0.0; dinc = 0ull; dcorr = 0ull;
            #pragma unroll
            for (int w = 0; w < 8; w++) {
                dmse  += f_mse[w];
                diou  += f_iou[w];
                dinc  += f_inc[w];
                dcorr += f_corr[w];
            }
            double denom_mse = (double)(dinc * 4ull > 0ull ? dinc * 4ull : 1ull);
            double mse_mean = dmse / denom_mse;
            double denom_iou = (double)(dcorr > 0ull ? dcorr : 1ull);
            double iou_mean = diou / denom_iou;

            double res_full = iou_mean + (dinc > 0ull ? -mse_mean : 0.0);
            double res = (dcorr > 0ull) ? res_full : -mse_mean;
            out[0] = (float)res;

            g_count = 0u;  // reset for next graph replay
        }
    }
}

extern "C" void kernel_launch(void* const* d_in, const int* in_sizes, int n_in,
                              void* d_out, int out_size) {
    const float4* pr = (const float4*)d_in[0];
    const float4* gt = (const float4*)d_in[1];
    int n = in_sizes[0] / 4;  // boxes

    static bool attr_set = false;
    if (!attr_set) {
        cudaFuncSetAttribute(iou_tma_kernel,
                             cudaFuncAttributeMaxDynamicSharedMemorySize, SMEM_TOTAL);
        attr_set = true;
    }

    int blocks = GRID_BLOCKS;
    int tiles = n / TILE;
    if (tiles < 1) tiles = 1;
    if (blocks > tiles) blocks = tiles;

    iou_tma_kernel<<<blocks, NTHREADS, SMEM_TOTAL>>>(pr, gt, n, (float*)d_out);
}